// round 2
// baseline (speedup 1.0000x reference)
#include <cuda_runtime.h>

// Problem shape (fixed by the dataset): B=4, S=2048, H=D=2048
#define B_ 4
#define S_ 2048
#define H_ 2048
#define M_ (B_ * S_)   // 8192 rows (b*s)
#define N_ H_          // 2048
#define K_ H_          // 2048

// -------- scratch (static device arrays; no allocation APIs anywhere) --------
__device__ float g_xk[(size_t)M_ * H_];
__device__ float g_xv[(size_t)M_ * H_];
__device__ float g_xr[(size_t)M_ * H_];
__device__ float g_k [(size_t)M_ * H_];
__device__ float g_v [(size_t)M_ * H_];
__device__ float g_r [(size_t)M_ * H_];
__device__ float g_y [(size_t)M_ * H_];

// -------- packed f32x2 helpers (FFMA2 path, sm_100+) --------
__device__ __forceinline__ void fma2(unsigned long long& c, unsigned long long a,
                                     unsigned long long b) {
    asm("fma.rn.f32x2 %0, %1, %2, %0;" : "+l"(c) : "l"(a), "l"(b));
}
__device__ __forceinline__ unsigned long long pack2(float lo, float hi) {
    unsigned long long r;
    asm("mov.b64 %0, {%1, %2};" : "=l"(r)
        : "r"(__float_as_uint(lo)), "r"(__float_as_uint(hi)));
    return r;
}
__device__ __forceinline__ unsigned long long dup2(float x) {
    unsigned long long r;
    asm("mov.b64 %0, {%1, %1};" : "=l"(r) : "r"(__float_as_uint(x)));
    return r;
}
__device__ __forceinline__ float2 unpack2(unsigned long long v) {
    unsigned int lo, hi;
    asm("mov.b64 {%0, %1}, %2;" : "=r"(lo), "=r"(hi) : "l"(v));
    float2 f;
    f.x = __uint_as_float(lo);
    f.y = __uint_as_float(hi);
    return f;
}

// ============================================================================
// Kernel 1: time-shift mix.  xk/xv/xr = shifted + mix*(hidden - shifted)
// ============================================================================
__global__ void mix_kernel(const float* __restrict__ hidden,
                           const float* __restrict__ tmk,
                           const float* __restrict__ tmv,
                           const float* __restrict__ tmr) {
    const int H4 = H_ / 4;
    int i = blockIdx.x * blockDim.x + threadIdx.x;  // float4 index
    int h4  = i % H4;
    int row = i / H4;            // b*S + s
    int s   = row & (S_ - 1);

    float4 cur = ((const float4*)hidden)[i];
    float4 sh  = make_float4(0.f, 0.f, 0.f, 0.f);
    if (s != 0) sh = ((const float4*)hidden)[i - H4];

    float4 mk = ((const float4*)tmk)[h4];
    float4 mv = ((const float4*)tmv)[h4];
    float4 mr = ((const float4*)tmr)[h4];

    float dx = cur.x - sh.x, dy = cur.y - sh.y, dz = cur.z - sh.z, dw = cur.w - sh.w;

    float4 ok, ov, orr;
    ok.x = fmaf(mk.x, dx, sh.x); ok.y = fmaf(mk.y, dy, sh.y);
    ok.z = fmaf(mk.z, dz, sh.z); ok.w = fmaf(mk.w, dw, sh.w);
    ov.x = fmaf(mv.x, dx, sh.x); ov.y = fmaf(mv.y, dy, sh.y);
    ov.z = fmaf(mv.z, dz, sh.z); ov.w = fmaf(mv.w, dw, sh.w);
    orr.x = fmaf(mr.x, dx, sh.x); orr.y = fmaf(mr.y, dy, sh.y);
    orr.z = fmaf(mr.z, dz, sh.z); orr.w = fmaf(mr.w, dw, sh.w);

    ((float4*)g_xk)[i] = ok;
    ((float4*)g_xv)[i] = ov;
    ((float4*)g_xr)[i] = orr;
}

// ============================================================================
// Kernel 2: SGEMM  C[M,N] = A[M,K] * W[N,K]^T   (both operands K-major)
// 128x128x16 tile, 256 threads, 8x8 per thread, FFMA2 inner product,
// register-prefetch double buffering.
//   which==0: A=g_xk, C=g_k          which==1: A=g_xv, C=g_v
//   which==2: A=g_xr, C=g_r (sigmoid) which==3: A=g_y,  C=Cout
// ============================================================================
#define BK 16
#define NKITER (K_ / BK)

__global__ __launch_bounds__(256, 2)
void sgemm_kernel(int which, const float* __restrict__ W, float* __restrict__ Cout) {
    const float* A;
    float* C;
    bool sig = false;
    if (which == 0)      { A = g_xk; C = g_k; }
    else if (which == 1) { A = g_xv; C = g_v; }
    else if (which == 2) { A = g_xr; C = g_r; sig = true; }
    else                 { A = g_y;  C = Cout; }

    __shared__ float As[BK][128];
    __shared__ float Bs[BK][128];

    const int tid = threadIdx.x;
    const int tx = tid & 15;       // 0..15 -> 8 cols each
    const int ty = tid >> 4;       // 0..15 -> 8 rows each

    const int lrow = tid >> 2;         // 0..63
    const int lcol = (tid & 3) * 4;    // 0,4,8,12

    const float* Abase = A + (size_t)blockIdx.y * 128 * K_;
    const float* Bbase = W + (size_t)blockIdx.x * 128 * K_;

    float4 pa0, pa1, pb0, pb1;

    // accumulators: rows packed in pairs -> acc[i2][j] = {row 2*i2, row 2*i2+1} x col j
    unsigned long long acc[4][8];
#pragma unroll
    for (int i = 0; i < 4; ++i)
#pragma unroll
        for (int j = 0; j < 8; ++j) acc[i][j] = 0ull;

    // --- prologue: load tile 0 ---
    {
        const float* Ar = Abase + (size_t)lrow * K_ + lcol;
        const float* Br = Bbase + (size_t)lrow * K_ + lcol;
        pa0 = *(const float4*)(Ar);
        pa1 = *(const float4*)(Ar + (size_t)64 * K_);
        pb0 = *(const float4*)(Br);
        pb1 = *(const float4*)(Br + (size_t)64 * K_);
    }
    As[lcol + 0][lrow] = pa0.x; As[lcol + 1][lrow] = pa0.y;
    As[lcol + 2][lrow] = pa0.z; As[lcol + 3][lrow] = pa0.w;
    As[lcol + 0][lrow + 64] = pa1.x; As[lcol + 1][lrow + 64] = pa1.y;
    As[lcol + 2][lrow + 64] = pa1.z; As[lcol + 3][lrow + 64] = pa1.w;
    Bs[lcol + 0][lrow] = pb0.x; Bs[lcol + 1][lrow] = pb0.y;
    Bs[lcol + 2][lrow] = pb0.z; Bs[lcol + 3][lrow] = pb0.w;
    Bs[lcol + 0][lrow + 64] = pb1.x; Bs[lcol + 1][lrow + 64] = pb1.y;
    Bs[lcol + 2][lrow + 64] = pb1.z; Bs[lcol + 3][lrow + 64] = pb1.w;
    __syncthreads();

    for (int kt = 0; kt < NKITER; ++kt) {
        // prefetch next tile into registers (overlaps compute)
        if (kt + 1 < NKITER) {
            const float* Ar = Abase + (size_t)lrow * K_ + (kt + 1) * BK + lcol;
            const float* Br = Bbase + (size_t)lrow * K_ + (kt + 1) * BK + lcol;
            pa0 = *(const float4*)(Ar);
            pa1 = *(const float4*)(Ar + (size_t)64 * K_);
            pb0 = *(const float4*)(Br);
            pb1 = *(const float4*)(Br + (size_t)64 * K_);
        }

#pragma unroll
        for (int kk = 0; kk < BK; ++kk) {
            float4 a0 = *(const float4*)&As[kk][ty * 8];
            float4 a1 = *(const float4*)&As[kk][ty * 8 + 4];
            float4 b0 = *(const float4*)&Bs[kk][tx * 8];
            float4 b1 = *(const float4*)&Bs[kk][tx * 8 + 4];

            unsigned long long ap[4];
            ap[0] = pack2(a0.x, a0.y); ap[1] = pack2(a0.z, a0.w);
            ap[2] = pack2(a1.x, a1.y); ap[3] = pack2(a1.z, a1.w);

            unsigned long long bd[8];
            bd[0] = dup2(b0.x); bd[1] = dup2(b0.y); bd[2] = dup2(b0.z); bd[3] = dup2(b0.w);
            bd[4] = dup2(b1.x); bd[5] = dup2(b1.y); bd[6] = dup2(b1.z); bd[7] = dup2(b1.w);

#pragma unroll
            for (int i2 = 0; i2 < 4; ++i2)
#pragma unroll
                for (int j = 0; j < 8; ++j) fma2(acc[i2][j], ap[i2], bd[j]);
        }
        __syncthreads();

        if (kt + 1 < NKITER) {
            As[lcol + 0][lrow] = pa0.x; As[lcol + 1][lrow] = pa0.y;
            As[lcol + 2][lrow] = pa0.z; As[lcol + 3][lrow] = pa0.w;
            As[lcol + 0][lrow + 64] = pa1.x; As[lcol + 1][lrow + 64] = pa1.y;
            As[lcol + 2][lrow + 64] = pa1.z; As[lcol + 3][lrow + 64] = pa1.w;
            Bs[lcol + 0][lrow] = pb0.x; Bs[lcol + 1][lrow] = pb0.y;
            Bs[lcol + 2][lrow] = pb0.z; Bs[lcol + 3][lrow] = pb0.w;
            Bs[lcol + 0][lrow + 64] = pb1.x; Bs[lcol + 1][lrow + 64] = pb1.y;
            Bs[lcol + 2][lrow + 64] = pb1.z; Bs[lcol + 3][lrow + 64] = pb1.w;
            __syncthreads();
        }
    }

    // --- epilogue ---
    const size_t R0 = (size_t)blockIdx.y * 128 + ty * 8;
    const size_t C0 = (size_t)blockIdx.x * 128 + tx * 8;
#pragma unroll
    for (int rr = 0; rr < 8; ++rr) {
        float vals[8];
#pragma unroll
        for (int j = 0; j < 8; ++j) {
            float2 p = unpack2(acc[rr >> 1][j]);
            vals[j] = (rr & 1) ? p.y : p.x;
        }
        if (sig) {
#pragma unroll
            for (int j = 0; j < 8; ++j) vals[j] = 1.f / (1.f + __expf(-vals[j]));
        }
        float4* cp = (float4*)(C + (R0 + rr) * N_ + C0);
        cp[0] = make_float4(vals[0], vals[1], vals[2], vals[3]);
        cp[1] = make_float4(vals[4], vals[5], vals[6], vals[7]);
    }
}

// ============================================================================
// Kernel 3: WKV scan. One thread per (b,d) channel; sequential over S.
// Writes y = r * wkv directly.
// ============================================================================
__global__ void wkv_kernel(const float* __restrict__ time_decay,
                           const float* __restrict__ time_first) {
    int t = blockIdx.x * blockDim.x + threadIdx.x;  // 0 .. B*D-1
    int b = t >> 11;          // / 2048
    int d = t & (H_ - 1);

    float w  = -__expf(time_decay[d]);
    float tf = time_first[d];

    float num = 0.f, den = 0.f, mx = -1e38f;
    size_t idx = (size_t)b * S_ * H_ + d;

    for (int s = 0; s < S_; ++s, idx += H_) {
        float k = g_k[idx];
        float v = g_v[idx];
        float r = g_r[idx];

        float ktf = k + tf;
        float mo  = fmaxf(mx, ktf);
        float e1  = __expf(mx - mo);
        float e2  = __expf(ktf - mo);
        float out = __fdividef(e1 * num + e2 * v, e1 * den + e2);
        g_y[idx] = r * out;

        float mw  = mx + w;
        float mn  = fmaxf(mw, k);
        float e1n = __expf(mw - mn);
        float e2n = __expf(k - mn);
        num = e1n * num + e2n * v;
        den = e1n * den + e2n;
        mx  = mn;
    }
}

// ============================================================================
// Launch
// ============================================================================
extern "C" void kernel_launch(void* const* d_in, const int* in_sizes, int n_in,
                              void* d_out, int out_size) {
    const float* hidden     = (const float*)d_in[0];
    const float* time_decay = (const float*)d_in[1];
    const float* time_first = (const float*)d_in[2];
    const float* tmk        = (const float*)d_in[3];
    const float* tmv        = (const float*)d_in[4];
    const float* tmr        = (const float*)d_in[5];
    const float* Wk         = (const float*)d_in[6];
    const float* Wv         = (const float*)d_in[7];
    const float* Wr         = (const float*)d_in[8];
    const float* Wo         = (const float*)d_in[9];
    float* out              = (float*)d_out;

    // 1) time-shift mix
    {
        int total4 = M_ * H_ / 4;                  // 4,194,304
        mix_kernel<<<total4 / 256, 256>>>(hidden, tmk, tmv, tmr);
    }

    // 2) three projection GEMMs
    dim3 gg(N_ / 128, M_ / 128);                   // (16, 64)
    sgemm_kernel<<<gg, 256>>>(0, Wk, nullptr);
    sgemm_kernel<<<gg, 256>>>(1, Wv, nullptr);
    sgemm_kernel<<<gg, 256>>>(2, Wr, nullptr);

    // 3) WKV scan (+ multiply by r)
    wkv_kernel<<<(B_ * H_) / 64, 64>>>(time_decay, time_first);

    // 4) output GEMM
    sgemm_kernel<<<gg, 256>>>(3, Wo, out);
}

// round 4
// speedup vs baseline: 1.4382x; 1.4382x over previous
#include <cuda_runtime.h>
#include <cuda_bf16.h>
#include <cstdint>

// Shapes: B=4, S=2048, H=D=2048
#define B_ 4
#define S_ 2048
#define H_ 2048
#define M_ (B_ * S_)   // 8192
#define N_ H_
#define K_ H_

// ---------------- scratch (static device arrays, no allocation) -------------
__device__ __nv_bfloat16 g_xkh[(size_t)M_ * H_], g_xkl[(size_t)M_ * H_];
__device__ __nv_bfloat16 g_xvh[(size_t)M_ * H_], g_xvl[(size_t)M_ * H_];
__device__ __nv_bfloat16 g_xrh[(size_t)M_ * H_], g_xrl[(size_t)M_ * H_];
__device__ __nv_bfloat16 g_yh [(size_t)M_ * H_], g_yl [(size_t)M_ * H_];
__device__ __nv_bfloat16 g_wh[4][(size_t)N_ * K_];
__device__ __nv_bfloat16 g_wl[4][(size_t)N_ * K_];
__device__ float g_k[(size_t)M_ * H_];
__device__ float g_v[(size_t)M_ * H_];
__device__ float g_r[(size_t)M_ * H_];

// ---------------- helpers ----------------
__device__ __forceinline__ uint32_t smem_u32(const void* p) {
    uint32_t a;
    asm("{ .reg .u64 t; cvta.to.shared.u64 t, %1; cvt.u32.u64 %0, t; }"
        : "=r"(a) : "l"(p));
    return a;
}
__device__ __forceinline__ void cpasync16(uint32_t dst, const void* src) {
    asm volatile("cp.async.cg.shared.global [%0], [%1], 16;" :: "r"(dst), "l"(src));
}
__device__ __forceinline__ void cp_commit() {
    asm volatile("cp.async.commit_group;" ::: "memory");
}
template <int N> __device__ __forceinline__ void cp_wait() {
    asm volatile("cp.async.wait_group %0;" :: "n"(N) : "memory");
}
__device__ __forceinline__ void mma16816(float* c, const uint32_t* a, const uint32_t* b) {
    asm volatile(
        "mma.sync.aligned.m16n8k16.row.col.f32.bf16.bf16.f32 "
        "{%0,%1,%2,%3}, {%4,%5,%6,%7}, {%8,%9}, {%0,%1,%2,%3};"
        : "+f"(c[0]), "+f"(c[1]), "+f"(c[2]), "+f"(c[3])
        : "r"(a[0]), "r"(a[1]), "r"(a[2]), "r"(a[3]), "r"(b[0]), "r"(b[1]));
}
__device__ __forceinline__ void split_bf(float x, __nv_bfloat16& h, __nv_bfloat16& l) {
    h = __float2bfloat16(x);
    l = __float2bfloat16(x - __bfloat162float(h));
}

// ============================================================================
// Kernel: convert one W matrix (fp32 [2048x2048]) to bf16 hi/lo
// ============================================================================
__global__ void convw_kernel(const float* __restrict__ W, int widx) {
    int i = blockIdx.x * blockDim.x + threadIdx.x;   // float4 index
    float4 w = ((const float4*)W)[i];
    __nv_bfloat16 h0, l0, h1, l1, h2, l2, h3, l3;
    split_bf(w.x, h0, l0); split_bf(w.y, h1, l1);
    split_bf(w.z, h2, l2); split_bf(w.w, h3, l3);
    __nv_bfloat162* ph = (__nv_bfloat162*)g_wh[widx];
    __nv_bfloat162* pl = (__nv_bfloat162*)g_wl[widx];
    ph[2 * i]     = __nv_bfloat162(h0, h1);
    ph[2 * i + 1] = __nv_bfloat162(h2, h3);
    pl[2 * i]     = __nv_bfloat162(l0, l1);
    pl[2 * i + 1] = __nv_bfloat162(l2, l3);
}

// ============================================================================
// Kernel: time-shift mix -> bf16 hi/lo of xk, xv, xr
// ============================================================================
__global__ void mix_kernel(const float* __restrict__ hidden,
                           const float* __restrict__ tmk,
                           const float* __restrict__ tmv,
                           const float* __restrict__ tmr) {
    const int H4 = H_ / 4;
    int i = blockIdx.x * blockDim.x + threadIdx.x;   // float4 index
    int h4  = i % H4;
    int row = i / H4;
    int s   = row & (S_ - 1);

    float4 cur = ((const float4*)hidden)[i];
    float4 sh  = make_float4(0.f, 0.f, 0.f, 0.f);
    if (s != 0) sh = ((const float4*)hidden)[i - H4];

    float4 mk = ((const float4*)tmk)[h4];
    float4 mv = ((const float4*)tmv)[h4];
    float4 mr = ((const float4*)tmr)[h4];

    float dx = cur.x - sh.x, dy = cur.y - sh.y, dz = cur.z - sh.z, dw = cur.w - sh.w;

    float vals[3][4];
    vals[0][0] = fmaf(mk.x, dx, sh.x); vals[0][1] = fmaf(mk.y, dy, sh.y);
    vals[0][2] = fmaf(mk.z, dz, sh.z); vals[0][3] = fmaf(mk.w, dw, sh.w);
    vals[1][0] = fmaf(mv.x, dx, sh.x); vals[1][1] = fmaf(mv.y, dy, sh.y);
    vals[1][2] = fmaf(mv.z, dz, sh.z); vals[1][3] = fmaf(mv.w, dw, sh.w);
    vals[2][0] = fmaf(mr.x, dx, sh.x); vals[2][1] = fmaf(mr.y, dy, sh.y);
    vals[2][2] = fmaf(mr.z, dz, sh.z); vals[2][3] = fmaf(mr.w, dw, sh.w);

    __nv_bfloat162* dh[3] = {(__nv_bfloat162*)g_xkh, (__nv_bfloat162*)g_xvh, (__nv_bfloat162*)g_xrh};
    __nv_bfloat162* dl[3] = {(__nv_bfloat162*)g_xkl, (__nv_bfloat162*)g_xvl, (__nv_bfloat162*)g_xrl};
#pragma unroll
    for (int t = 0; t < 3; ++t) {
        __nv_bfloat16 h0, l0, h1, l1, h2, l2, h3, l3;
        split_bf(vals[t][0], h0, l0); split_bf(vals[t][1], h1, l1);
        split_bf(vals[t][2], h2, l2); split_bf(vals[t][3], h3, l3);
        dh[t][2 * i]     = __nv_bfloat162(h0, h1);
        dh[t][2 * i + 1] = __nv_bfloat162(h2, h3);
        dl[t][2 * i]     = __nv_bfloat162(l0, l1);
        dl[t][2 * i + 1] = __nv_bfloat162(l2, l3);
    }
}

// ============================================================================
// HMMA GEMM: C[M,N] = A[M,K']*B[N,K']^T, bf16x3 split as virtual K' = 3*2048.
// CTA 128x128, 256 threads (8 warps, 2x4), warp tile 64x32 via m16n8k16.
// BK=16, 3-stage cp.async pipeline, padded smem rows (24 bf16) -> no conflicts.
// ============================================================================
#define NST 3
#define BK 16
#define LDS_ROW 24                     // 16 data + 8 pad bf16 (48B row stride)
#define NKSTEP (3 * K_ / BK)           // 384

__device__ __nv_bfloat16* pick(int which, const __nv_bfloat16** Ah, const __nv_bfloat16** Al,
                               const __nv_bfloat16** Bh, const __nv_bfloat16** Bl);

__global__ __launch_bounds__(256) void gemm_hmma(int which, float* __restrict__ Cout) {
    __shared__ __nv_bfloat16 As[NST][128][LDS_ROW];
    __shared__ __nv_bfloat16 Bs[NST][128][LDS_ROW];

    const __nv_bfloat16 *Ah, *Al, *Bh, *Bl;
    float* C;
    bool sig = false;
    if (which == 0)      { Ah = g_xkh; Al = g_xkl; Bh = g_wh[0]; Bl = g_wl[0]; C = g_k; }
    else if (which == 1) { Ah = g_xvh; Al = g_xvl; Bh = g_wh[1]; Bl = g_wl[1]; C = g_v; }
    else if (which == 2) { Ah = g_xrh; Al = g_xrl; Bh = g_wh[2]; Bl = g_wl[2]; C = g_r; sig = true; }
    else                 { Ah = g_yh;  Al = g_yl;  Bh = g_wh[3]; Bl = g_wl[3]; C = Cout; }

    const int tid  = threadIdx.x;
    const int wid  = tid >> 5;
    const int lane = tid & 31;
    const int wm   = wid >> 2;       // 0..1 : 64-row half
    const int wn   = wid & 3;        // 0..3 : 32-col strip
    const int g    = lane >> 2;      // 0..7
    const int t4   = lane & 3;       // 0..3

    const int rowA0 = blockIdx.y * 128;
    const int rowB0 = blockIdx.x * 128;

    // gmem load mapping: 256 threads x 16B; id -> (row, 16B-half)
    const int lr = tid >> 1;         // 0..127
    const int lh = tid & 1;          // 0..1

    const uint32_t sA0 = smem_u32(&As[0][0][0]);
    const uint32_t sB0 = smem_u32(&Bs[0][0][0]);
    const uint32_t stgBytes = 128 * LDS_ROW * 2;

    auto load_stage = [&](int st, int slot) {
        // phase: 0 -> Ah*Bh, 1 -> Ah*Bl, 2 -> Al*Bh
        int phase = st >> 7;               // st / 128
        int k0 = (st & 127) * BK;
        const __nv_bfloat16* Ap = (phase < 2) ? Ah : Al;
        const __nv_bfloat16* Bp = (phase == 1) ? Bl : Bh;
        cpasync16(sA0 + slot * stgBytes + lr * (LDS_ROW * 2) + lh * 16,
                  Ap + (size_t)(rowA0 + lr) * K_ + k0 + lh * 8);
        cpasync16(sB0 + slot * stgBytes + lr * (LDS_ROW * 2) + lh * 16,
                  Bp + (size_t)(rowB0 + lr) * K_ + k0 + lh * 8);
    };

    float acc[4][4][4];
#pragma unroll
    for (int i = 0; i < 4; ++i)
#pragma unroll
        for (int j = 0; j < 4; ++j)
#pragma unroll
            for (int r = 0; r < 4; ++r) acc[i][j][r] = 0.f;

    load_stage(0, 0); cp_commit();
    load_stage(1, 1); cp_commit();

    for (int kt = 0; kt < NKSTEP; ++kt) {
        const int slot = kt % NST;
        if (kt + 1 < NKSTEP) cp_wait<1>(); else cp_wait<0>();
        __syncthreads();

        // fragments
        uint32_t afr[4][4];
#pragma unroll
        for (int mt = 0; mt < 4; ++mt) {
            int r0 = wm * 64 + mt * 16 + g;
            afr[mt][0] = *(const uint32_t*)&As[slot][r0][2 * t4];
            afr[mt][1] = *(const uint32_t*)&As[slot][r0 + 8][2 * t4];
            afr[mt][2] = *(const uint32_t*)&As[slot][r0][2 * t4 + 8];
            afr[mt][3] = *(const uint32_t*)&As[slot][r0 + 8][2 * t4 + 8];
        }
        uint32_t bfr[4][2];
#pragma unroll
        for (int nt = 0; nt < 4; ++nt) {
            int n0 = wn * 32 + nt * 8 + g;
            bfr[nt][0] = *(const uint32_t*)&Bs[slot][n0][2 * t4];
            bfr[nt][1] = *(const uint32_t*)&Bs[slot][n0][2 * t4 + 8];
        }
#pragma unroll
        for (int mt = 0; mt < 4; ++mt)
#pragma unroll
            for (int nt = 0; nt < 4; ++nt)
                mma16816(acc[mt][nt], afr[mt], bfr[nt]);

        __syncthreads();
        if (kt + 2 < NKSTEP) { load_stage(kt + 2, (kt + 2) % NST); cp_commit(); }
    }

    // epilogue: c0,c1 -> (row, 2t..2t+1); c2,c3 -> (row+8, ...)
#pragma unroll
    for (int mt = 0; mt < 4; ++mt) {
        size_t row = (size_t)rowA0 + wm * 64 + mt * 16 + g;
#pragma unroll
        for (int nt = 0; nt < 4; ++nt) {
            int col = rowB0 + wn * 32 + nt * 8 + 2 * t4;
            float2 lo = make_float2(acc[mt][nt][0], acc[mt][nt][1]);
            float2 hi = make_float2(acc[mt][nt][2], acc[mt][nt][3]);
            if (sig) {
                lo.x = 1.f / (1.f + __expf(-lo.x)); lo.y = 1.f / (1.f + __expf(-lo.y));
                hi.x = 1.f / (1.f + __expf(-hi.x)); hi.y = 1.f / (1.f + __expf(-hi.y));
            }
            *(float2*)(C + row * N_ + col) = lo;
            *(float2*)(C + (row + 8) * N_ + col) = hi;
        }
    }
}

// ============================================================================
// WKV scan: one thread per (b,d); writes y = r*wkv as bf16 hi/lo
// ============================================================================
__global__ void wkv_kernel(const float* __restrict__ time_decay,
                           const float* __restrict__ time_first) {
    int t = blockIdx.x * blockDim.x + threadIdx.x;
    int b = t >> 11;
    int d = t & (H_ - 1);

    float w  = -__expf(time_decay[d]);
    float tf = time_first[d];

    float num = 0.f, den = 0.f, mx = -1e38f;
    size_t idx = (size_t)b * S_ * H_ + d;

    for (int s = 0; s < S_; ++s, idx += H_) {
        float k = g_k[idx];
        float v = g_v[idx];
        float r = g_r[idx];

        float ktf = k + tf;
        float mo  = fmaxf(mx, ktf);
        float e1  = __expf(mx - mo);
        float e2  = __expf(ktf - mo);
        float out = __fdividef(e1 * num + e2 * v, e1 * den + e2);
        float y = r * out;
        __nv_bfloat16 h, l;
        split_bf(y, h, l);
        g_yh[idx] = h;
        g_yl[idx] = l;

        float mw  = mx + w;
        float mn  = fmaxf(mw, k);
        float e1n = __expf(mw - mn);
        float e2n = __expf(k - mn);
        num = e1n * num + e2n * v;
        den = e1n * den + e2n;
        mx  = mn;
    }
}

// ============================================================================
// Launch
// ============================================================================
extern "C" void kernel_launch(void* const* d_in, const int* in_sizes, int n_in,
                              void* d_out, int out_size) {
    const float* hidden     = (const float*)d_in[0];
    const float* time_decay = (const float*)d_in[1];
    const float* time_first = (const float*)d_in[2];
    const float* tmk        = (const float*)d_in[3];
    const float* tmv        = (const float*)d_in[4];
    const float* tmr        = (const float*)d_in[5];
    const float* Wk         = (const float*)d_in[6];
    const float* Wv         = (const float*)d_in[7];
    const float* Wr         = (const float*)d_in[8];
    const float* Wo         = (const float*)d_in[9];
    float* out              = (float*)d_out;

    // 0) weight conversion to bf16 hi/lo
    {
        int blocks = (N_ * K_ / 4) / 256;
        convw_kernel<<<blocks, 256>>>(Wk, 0);
        convw_kernel<<<blocks, 256>>>(Wv, 1);
        convw_kernel<<<blocks, 256>>>(Wr, 2);
        convw_kernel<<<blocks, 256>>>(Wo, 3);
    }

    // 1) time-shift mix (fp32 -> bf16 hi/lo)
    mix_kernel<<<(M_ * H_ / 4) / 256, 256>>>(hidden, tmk, tmv, tmr);

    // 2) projection GEMMs (HMMA)
    dim3 gg(N_ / 128, M_ / 128);   // (16, 64)
    gemm_hmma<<<gg, 256>>>(0, nullptr);
    gemm_hmma<<<gg, 256>>>(1, nullptr);
    gemm_hmma<<<gg, 256>>>(2, nullptr);

    // 3) WKV scan (writes y hi/lo)
    wkv_kernel<<<256, 32>>>(time_decay, time_first);

    // 4) output GEMM
    gemm_hmma<<<gg, 256>>>(3, out);
}